// round 8
// baseline (speedup 1.0000x reference)
#include <cuda_runtime.h>
#include <cuda_bf16.h>
#include <cstdint>

// ---- problem constants ----
#define T1n 128
#define T2n 512
#define TPn 8
#define Hn  16
#define Kn  4
#define Cn  129   // 2*K*H+1
#define Dn  256

// ---- device scratch ----
__device__ uint2 g_pack[T1n * TPn * T2n];  // {bits(aw sign-folded), |pos| | maskbit}
__device__ float g_mB2[T1n * T2n];         // m * B^2  (B = dsum/8 - val)

// ---------------------------------------------------------------------------
// K1: fused val + pack build. Grid (32,4): block = 4 i-rows x 128 j-cols.
// ---------------------------------------------------------------------------
__global__ __launch_bounds__(512) void k_valbuild(const float* __restrict__ e1,
                                                  const float* __restrict__ e2,
                                                  const int* __restrict__ sta,
                                                  const int* __restrict__ pos,
                                                  const unsigned* __restrict__ mask) {
    int i0 = blockIdx.x * 4;
    int j0 = blockIdx.y * 128;
    int tid = threadIdx.x;
    int q = tid >> 7, r = tid & 127;
    int i = i0 + q, j = j0 + r;

    __shared__ float s1[4][Dn];
    __shared__ float red[4][4];
    __shared__ float sinv[4];
    __shared__ int   s_sta[4][TPn];

    float a0 = e1[i * Dn + r];
    float a1 = e1[i * Dn + 128 + r];
    float ss = a0 * a0 + a1 * a1;
    for (int o = 16; o; o >>= 1) ss += __shfl_down_sync(0xffffffffu, ss, o);
    if ((r & 31) == 0) red[q][r >> 5] = ss;
    if (tid < 32) s_sta[tid >> 3][tid & 7] = sta[(i0 + (tid >> 3)) * TPn + (tid & 7)];
    __syncthreads();
    if (tid < 4) sinv[tid] = rsqrtf(red[tid][0] + red[tid][1] + red[tid][2] + red[tid][3]);
    __syncthreads();
    float inv = sinv[q];
    s1[q][r] = a0 * inv;
    s1[q][r + 128] = a1 * inv;
    __syncthreads();

    const float4* row  = (const float4*)(e2 + j * Dn);
    const float4* arow = (const float4*)(&s1[q][0]);
    float dot = 0.f, ssq = 0.f;
    #pragma unroll 8
    for (int kk = 0; kk < Dn / 4; kk++) {
        float4 b = row[kk];
        float4 a = arow[kk];
        dot = fmaf(a.x, b.x, dot); ssq = fmaf(b.x, b.x, ssq);
        dot = fmaf(a.y, b.y, dot); ssq = fmaf(b.y, b.y, ssq);
        dot = fmaf(a.z, b.z, dot); ssq = fmaf(b.z, b.z, ssq);
        dot = fmaf(a.w, b.w, dot); ssq = fmaf(b.w, b.w, ssq);
    }
    float val = dot * rsqrtf(ssq);

    int4 p0 = ((const int4*)pos)[j * 2];
    int4 p1 = ((const int4*)pos)[j * 2 + 1];
    int pv[TPn] = {p0.x, p0.y, p0.z, p0.w, p1.x, p1.y, p1.z, p1.w};
    bool m = (mask[i * T2n + j] != 0u);

    float dis[TPn];
    int   ab[TPn];
    float dsum = 0.f;
    #pragma unroll
    for (int tt = 0; tt < TPn; tt++) {
        int stt = s_sta[q][tt];
        int a = stt < 0 ? -stt : stt;
        int b = pv[tt] < 0 ? -pv[tt] : pv[tt];
        ab[tt] = b;
        float sg = ((stt ^ pv[tt]) < 0) ? -1.0f : 1.0f;
        int v = (a ^ b) + 1;
        int p; asm("bfind.u32 %0, %1;" : "=r"(p) : "r"(v));
        float d = sg * (float)(15 - p) * (1.0f / 16.0f);
        dis[tt] = d;
        dsum += d;
    }

    float B = dsum * 0.125f - val;
    g_mB2[i * T2n + j] = m ? B * B : 0.0f;

    unsigned mtag = m ? 0u : 0x80000000u;
    #pragma unroll
    for (int tt = 0; tt < TPn; tt++) {
        float A = (dsum - dis[tt]) * 0.125f - val;
        unsigned awb = __float_as_uint(A * (1.0f / 128.0f)) ^
                       ((unsigned)pv[tt] & 0x80000000u);
        g_pack[(i * TPn + tt) * T2n + j] =
            make_uint2(awb, (unsigned)ab[tt] | mtag);
    }
}

// ---------------------------------------------------------------------------
// K2: bucket-aggregated loss. Grid (i,t) = (128,8); 256 threads (8 warps).
//   Build: load 512 pack entries; deterministic counting sort of masked-in
//     entries into 32 buckets by ap>>11 (match_any ranks + warp-scan of
//     per-(warp,half) counts); per-bucket W_b (aw sums); SA; loss64 (t==0).
//   Per candidate (tid>>2; 4 threads/cand):
//     - 31 non-matching buckets: f from bucket-index XOR msb alone.
//     - matching bucket (ap>>11 == ac>>11): exact per-entry formula.
//     - ripple corrections: for p in [11,16], entries with ap == ac^(2^(p+1)-1)
//       have q = p+1 not p: scan that ap's bucket, dS2 = -aw, dSq = 2p-29.
//   Mirrors (65..128): loss± = SA + Sq/16384 ± 2*sc*S2.
// ---------------------------------------------------------------------------
__device__ __forceinline__ int make_cand(int c, int stav, const int* rm, int i, int t) {
    int h = c >> 2, k = c & 3;
    int r = rm[((i * Hn + h) * Kn + k) * TPn + t];
    return (stav ^ (1 << h)) ^ (r & ((1 << h) - 1));
}

__global__ __launch_bounds__(256, 6) void k_loss(const int* __restrict__ sta,
                                                 const int* __restrict__ rmask,
                                                 float* __restrict__ out) {
    int i = blockIdx.x, t = blockIdx.y;
    int tid = threadIdx.x;
    int lane = tid & 31, w = tid >> 5;          // 8 warps
    unsigned lt = (1u << lane) - 1u;

    __shared__ uint2 s_pk[T2n];                 // 4 KB, bucket-grouped
    __shared__ int   s_cm[16][32];              // counts [row = w*2+rr][bucket]
    __shared__ int   s_off[16][32];             // scatter offsets
    __shared__ int   s_bs[33];                  // bucket starts; s_bs[32] = cnt
    __shared__ float s_W[32];                   // per-bucket aw sums
    __shared__ float s_red[8], s_red64[8];
    __shared__ float s_SA, s_L64;

    // zero count matrix
    ((int*)s_cm)[tid] = 0;
    ((int*)s_cm)[256 + tid] = 0;
    __syncthreads();

    const uint2* gp = g_pack + (i * TPn + t) * T2n;

    uint2    pkR[2];
    int      bR[2], rankR[2];
    bool     mR[2];
    float    sacc = 0.f, l64 = 0.f;
    #pragma unroll
    for (int rr = 0; rr < 2; rr++) {
        uint2 pk = gp[rr * 256 + tid];
        bool m = ((int)pk.y) >= 0;
        int b = (int)((pk.y >> 11) & 31u);
        unsigned ball = __ballot_sync(0xffffffffu, m);
        unsigned same = __match_any_sync(0xffffffffu, b) & ball;
        int rank = __popc(same & lt);
        if (m && rank == 0) s_cm[w * 2 + rr][b] = __popc(same);
        if (m) { float aw = __uint_as_float(pk.x); sacc = fmaf(aw, aw, sacc); }
        pkR[rr] = pk; bR[rr] = b; rankR[rr] = rank; mR[rr] = m;
    }
    if (t == 0)
        l64 = g_mB2[i * T2n + tid] + g_mB2[i * T2n + 256 + tid];
    for (int o = 16; o; o >>= 1) {
        sacc += __shfl_down_sync(0xffffffffu, sacc, o);
        l64  += __shfl_down_sync(0xffffffffu, l64, o);
    }
    if (lane == 0) { s_red[w] = sacc; s_red64[w] = l64; }
    __syncthreads();

    // warp 0: scan; warp 1: SA/L64 totals
    if (tid < 32) {
        int rowpre[16];
        int tot = 0;
        #pragma unroll
        for (int row = 0; row < 16; row++) { rowpre[row] = tot; tot += s_cm[row][lane]; }
        int run = tot;
        #pragma unroll
        for (int o = 1; o < 32; o <<= 1) {
            int n = __shfl_up_sync(0xffffffffu, run, o);
            if (lane >= o) run += n;
        }
        int excl = run - tot;
        s_bs[lane] = excl;
        if (lane == 31) s_bs[32] = run;
        #pragma unroll
        for (int row = 0; row < 16; row++) s_off[row][lane] = excl + rowpre[row];
    } else if (tid == 32) {
        float sa = 0.f;
        #pragma unroll
        for (int x = 0; x < 8; x++) sa += s_red[x];
        s_SA = sa * 16384.0f;
    } else if (tid == 33) {
        float s64 = 0.f;
        #pragma unroll
        for (int x = 0; x < 8; x++) s64 += s_red64[x];
        s_L64 = s64;
    }
    __syncthreads();

    // scatter into bucket-grouped order
    #pragma unroll
    for (int rr = 0; rr < 2; rr++) {
        if (mR[rr])
            s_pk[s_off[w * 2 + rr][bR[rr]] + rankR[rr]] = pkR[rr];
    }
    __syncthreads();

    // per-bucket aw sums: warp w -> buckets 4w..4w+3, 8 lanes each
    {
        int b  = w * 4 + (lane >> 3);
        int l8 = lane & 7;
        int lo = s_bs[b], hi = s_bs[b + 1];
        float ws = 0.f;
        for (int k = lo + l8; k < hi; k += 8) ws += __uint_as_float(s_pk[k].x);
        ws += __shfl_down_sync(0xffffffffu, ws, 4, 8);
        ws += __shfl_down_sync(0xffffffffu, ws, 2, 8);
        ws += __shfl_down_sync(0xffffffffu, ws, 1, 8);
        if (l8 == 0) s_W[b] = ws;
    }
    __syncthreads();

    // ---- per-candidate ----
    int c  = tid >> 2;                 // 0..63
    int q4 = tid & 3;
    int stav = sta[i * TPn + t];
    int cand = make_cand(c, stav, rmask, i, t);
    unsigned ac = (unsigned)(cand < 0 ? -cand : cand);
    int acH = (int)(ac >> 11);         // 0..32

    float S2 = 0.f, Sq = 0.f;

    // (a) non-matching bucket aggregates (8 buckets per thread)
    #pragma unroll
    for (int u = 0; u < 8; u++) {
        int b = q4 * 8 + u;
        if (b != acH) {
            int xh = acH ^ b;                           // 1..63
            int pb; asm("bfind.u32 %0, %1;" : "=r"(pb) : "r"(xh));
            float f  = 8388612.0f - __int_as_float(pb | 0x4B000000);  // 4 - pb
            int   Nb = s_bs[b + 1] - s_bs[b];
            float fn = __int_as_float(Nb | 0x4B000000) - 8388608.0f;  // (float)Nb
            S2 = fmaf(s_W[b], f, S2);
            Sq = fmaf(fn, f * f, Sq);
        }
    }

    // (b) matching bucket: exact per-entry
    if (acH < 32) {
        int hi = s_bs[acH + 1];
        for (int k = s_bs[acH] + q4; k < hi; k += 4) {
            uint2 e = s_pk[k];
            unsigned v = (ac ^ e.y) + 1u;
            int qq; asm("bfind.u32 %0, %1;" : "=r"(qq) : "r"(v));
            float f = 8388623.0f - __int_as_float(qq | 0x4B000000);   // 15 - qq
            S2 = fmaf(__uint_as_float(e.x), f, S2);
            Sq = fmaf(f, f, Sq);
        }
    }

    // (c) ripple corrections: p in {11+q4, 15+q4 (if <=16)}
    #pragma unroll
    for (int pp = 0; pp < 2; pp++) {
        int p = 11 + q4 + pp * 4;
        if (p <= 16) {
            unsigned rv = ac ^ ((2u << p) - 1u);
            if (rv <= 65535u) {
                int bb = (int)(rv >> 11);
                int lo = s_bs[bb], hi = s_bs[bb + 1];
                float dq = (float)(2 * p - 29);
                for (int k = lo; k < hi; k++) {
                    uint2 e = s_pk[k];
                    if (e.y == rv) { S2 -= __uint_as_float(e.x); Sq += dq; }
                }
            }
        }
    }

    // reduce the 4-thread quad
    S2 += __shfl_down_sync(0xffffffffu, S2, 2, 4);
    S2 += __shfl_down_sync(0xffffffffu, S2, 1, 4);
    Sq += __shfl_down_sync(0xffffffffu, Sq, 2, 4);
    Sq += __shfl_down_sync(0xffffffffu, Sq, 1, 4);

    if (q4 == 0) {
        float base = s_SA + Sq * (1.0f / 16384.0f);
        float sc   = cand < 0 ? -1.0f : 1.0f;
        float tw   = 2.0f * sc * S2;
        float lp   = base + tw;
        out[(i * Cn + c) * TPn + t] = lp;
        out[(i * Cn + 65 + c) * TPn + t] = (cand == 0) ? lp : (base - tw);
    }
    if (tid == 0 && t == 0) {
        float s64 = s_L64;
        #pragma unroll
        for (int tt = 0; tt < TPn; tt++)
            out[(i * Cn + 64) * TPn + tt] = s64;
    }
}

// ---------------------------------------------------------------------------
extern "C" void kernel_launch(void* const* d_in, const int* in_sizes, int n_in,
                              void* d_out, int out_size) {
    const float*    emb1 = (const float*)d_in[0];
    const float*    emb2 = (const float*)d_in[1];
    const int*      sta  = (const int*)d_in[2];
    const int*      pos  = (const int*)d_in[3];
    const unsigned* mask = (const unsigned*)d_in[4];
    const int*      rm   = (const int*)d_in[5];
    float*          out  = (float*)d_out;

    k_valbuild<<<dim3(32, 4), 512>>>(emb1, emb2, sta, pos, mask);
    k_loss<<<dim3(T1n, TPn), 256>>>(sta, rm, out);
}

// round 10
// speedup vs baseline: 1.5172x; 1.5172x over previous
#include <cuda_runtime.h>
#include <cuda_bf16.h>
#include <cstdint>

// ---- problem constants ----
#define T1n 128
#define T2n 512
#define TPn 8
#define Hn  16
#define Kn  4
#define Cn  129   // 2*K*H+1
#define Dn  256

// ---- device scratch ----
__device__ float  g_val[T1n * T2n];
__device__ uint2  g_pack[T1n * TPn * T2n];    // bucket-sorted compacted {awb, ap}
__device__ int    g_bs[T1n * TPn * 17];       // bucket starts (bs[16] = cnt)
__device__ float2 g_WN[T1n * TPn * 16];       // per-bucket {sum aw, (float)count}
__device__ float  g_SA[T1n * TPn];            // sum m*A^2
__device__ float  g_L64[T1n];                 // loss for c == sta

// ---------------------------------------------------------------------------
// K1: val_v via smem-tiled dot. Grid (8 i-tiles, 16 j-tiles); 512 threads.
// ---------------------------------------------------------------------------
__global__ __launch_bounds__(512) void k_val(const float* __restrict__ e1,
                                             const float* __restrict__ e2) {
    int i0 = blockIdx.x * 16;
    int j0 = blockIdx.y * 32;
    int tid = threadIdx.x;
    int il = tid >> 5, jl = tid & 31;
    int lane = tid & 31;

    __shared__ float2 s_e2[32][129];   // 256 floats + pad
    __shared__ float  s_inv1[16], s_inv2[32];

    {
        int r = tid >> 4, c = tid & 15;
        const float4* src = (const float4*)(e2 + (j0 + r) * Dn);
        #pragma unroll
        for (int mth = 0; mth < 4; mth++) {
            float4 v = src[c + 16 * mth];
            s_e2[r][(c + 16 * mth) * 2 + 0] = make_float2(v.x, v.y);
            s_e2[r][(c + 16 * mth) * 2 + 1] = make_float2(v.z, v.w);
        }
    }
    {
        int w = tid >> 5;
        const float4* src = (const float4*)(e1 + (i0 + w) * Dn);
        float4 a = src[lane * 2], b = src[lane * 2 + 1];
        float s = a.x*a.x + a.y*a.y + a.z*a.z + a.w*a.w
                + b.x*b.x + b.y*b.y + b.z*b.z + b.w*b.w;
        for (int o = 16; o; o >>= 1) s += __shfl_down_sync(0xffffffffu, s, o);
        if (lane == 0) s_inv1[w] = rsqrtf(s);
    }
    __syncthreads();
    {
        int r = tid >> 4, c = tid & 15;
        float s = 0.f;
        #pragma unroll
        for (int mth = 0; mth < 8; mth++) {
            float2 v = s_e2[r][c + 16 * mth];
            s = fmaf(v.x, v.x, fmaf(v.y, v.y, s));
        }
        #pragma unroll
        for (int o = 8; o; o >>= 1) s += __shfl_down_sync(0xffffffffu, s, o, 16);
        if (c == 0) s_inv2[r] = rsqrtf(s);
    }
    __syncthreads();

    const float4* arow = (const float4*)(e1 + (i0 + il) * Dn);
    float acc = 0.f;
    #pragma unroll 8
    for (int k4 = 0; k4 < 64; k4++) {
        float4 a = arow[k4];
        float2 b0 = s_e2[jl][2 * k4];
        float2 b1 = s_e2[jl][2 * k4 + 1];
        acc = fmaf(a.x, b0.x, acc);
        acc = fmaf(a.y, b0.y, acc);
        acc = fmaf(a.z, b1.x, acc);
        acc = fmaf(a.w, b1.y, acc);
    }
    g_val[(i0 + il) * T2n + j0 + jl] = acc * s_inv1[il] * s_inv2[jl];
}

// ---------------------------------------------------------------------------
// K2: build. Grid 128 (block per i); 512 threads (16 warps).
// ---------------------------------------------------------------------------
__global__ __launch_bounds__(512) void k_build(const int* __restrict__ sta,
                                               const int* __restrict__ pos,
                                               const unsigned* __restrict__ mask) {
    int i = blockIdx.x;
    int tid = threadIdx.x;
    int lane = tid & 31, w = tid >> 5;
    unsigned lt = (1u << lane) - 1u;

    __shared__ uint2 s_all[TPn][T2n];     // 32 KB
    __shared__ int   s_cm[TPn][16][16];   // [t][warp][bucket] counts -> offsets
    __shared__ int   s_bs[TPn][17];
    __shared__ int   s_st[TPn];
    __shared__ float s_red[16][9];

    if (tid < TPn) s_st[tid] = sta[i * TPn + tid];
    #pragma unroll
    for (int u = 0; u < 4; u++) ((int*)s_cm)[tid + 512 * u] = 0;
    __syncthreads();

    int j = tid;
    int4 p0 = ((const int4*)pos)[j * 2];
    int4 p1 = ((const int4*)pos)[j * 2 + 1];
    int pv[TPn] = {p0.x, p0.y, p0.z, p0.w, p1.x, p1.y, p1.z, p1.w};
    bool m = (mask[i * T2n + j] != 0u);
    float val = g_val[i * T2n + j];

    float dis[TPn];
    int   ab[TPn];
    float dsum = 0.f;
    #pragma unroll
    for (int tt = 0; tt < TPn; tt++) {
        int stt = s_st[tt];
        int a = stt < 0 ? -stt : stt;
        int b = pv[tt] < 0 ? -pv[tt] : pv[tt];
        ab[tt] = b;
        float sg = ((stt ^ pv[tt]) < 0) ? -1.0f : 1.0f;
        int v = (a ^ b) + 1;
        int p; asm("bfind.u32 %0, %1;" : "=r"(p) : "r"(v));
        float d = sg * (float)(15 - p) * (1.0f / 16.0f);
        dis[tt] = d;
        dsum += d;
    }

    // SA_t and L64 reductions
    {
        float red9[9];
        float B = dsum * 0.125f - val;
        red9[8] = m ? B * B : 0.0f;
        #pragma unroll
        for (int tt = 0; tt < TPn; tt++) {
            float A = (dsum - dis[tt]) * 0.125f - val;
            red9[tt] = m ? A * A : 0.0f;
        }
        #pragma unroll
        for (int o = 16; o; o >>= 1) {
            #pragma unroll
            for (int x = 0; x < 9; x++)
                red9[x] += __shfl_down_sync(0xffffffffu, red9[x], o);
        }
        if (lane == 0) {
            #pragma unroll
            for (int x = 0; x < 9; x++) s_red[w][x] = red9[x];
        }
    }

    // per-(t,warp,bucket) counts
    unsigned ball = __ballot_sync(0xffffffffu, m);
    int rank[TPn];
    #pragma unroll
    for (int tt = 0; tt < TPn; tt++) {
        int b = ab[tt] >> 12;
        unsigned same = __match_any_sync(0xffffffffu, b) & ball;
        rank[tt] = __popc(same & lt);
        if (m && rank[tt] == 0) s_cm[tt][w][b] = __popc(same);
    }
    __syncthreads();

    // warps 0..7 scan their t. ALL 32 lanes execute the width-16 shfl
    // (upper half computes duplicates); smem writes guarded by lane<16.
    if (w < TPn) {
        int t = w, b = lane & 15;
        int tot = 0;
        #pragma unroll
        for (int ww = 0; ww < 16; ww++) tot += s_cm[t][ww][b];
        int run = tot;
        #pragma unroll
        for (int o = 1; o < 16; o <<= 1) {
            int n = __shfl_up_sync(0xffffffffu, run, o, 16);
            if ((lane & 15) >= o) run += n;
        }
        if (lane < 16) {
            int excl = run - tot;
            s_bs[t][b] = excl;
            if (b == 15) s_bs[t][16] = run;
            int acc = excl;
            #pragma unroll
            for (int ww = 0; ww < 16; ww++) {
                int c = s_cm[t][ww][b]; s_cm[t][ww][b] = acc; acc += c;
            }
        }
    }
    // SA/L64 finalize
    if (tid >= 288 && tid < 297) {
        int x = tid - 288;
        float s = 0.f;
        #pragma unroll
        for (int ww = 0; ww < 16; ww++) s += s_red[ww][x];
        if (x < 8) g_SA[i * TPn + x] = s;
        else       g_L64[i] = s;
    }
    __syncthreads();

    // scatter all 8 t into smem
    if (m) {
        #pragma unroll
        for (int tt = 0; tt < TPn; tt++) {
            float A = (dsum - dis[tt]) * 0.125f - val;
            unsigned awb = __float_as_uint(A * (1.0f / 128.0f)) ^
                           ((unsigned)pv[tt] & 0x80000000u);
            int slot = s_cm[tt][w][ab[tt] >> 12] + rank[tt];
            s_all[tt][slot] = make_uint2(awb, (unsigned)ab[tt]);
        }
    }
    __syncthreads();

    // W/N per (t,b): 128 units x 4 threads
    {
        int unit = tid >> 2, q4 = tid & 3;
        int t = unit >> 4, b = unit & 15;
        int lo = s_bs[t][b], hi = s_bs[t][b + 1];
        float ws = 0.f;
        for (int k = lo + q4; k < hi; k += 4) ws += __uint_as_float(s_all[t][k].x);
        ws += __shfl_down_sync(0xffffffffu, ws, 2, 4);
        ws += __shfl_down_sync(0xffffffffu, ws, 1, 4);
        if (q4 == 0)
            g_WN[(i * TPn + t) * 16 + b] = make_float2(ws, (float)(hi - lo));
    }
    int cnt = s_bs[0][16];
    #pragma unroll
    for (int tt = 0; tt < TPn; tt++) {
        if (tid < cnt)
            g_pack[(i * TPn + tt) * T2n + tid] = s_all[tt][tid];
    }
    if (tid < TPn * 17) {
        int t = tid / 17, x = tid % 17;
        g_bs[(i * TPn + t) * 17 + x] = s_bs[t][x];
    }
}

// ---------------------------------------------------------------------------
// K3: loss. Grid (i,t) = (128,8); 256 threads; 4 threads per candidate.
// ---------------------------------------------------------------------------
__device__ __forceinline__ int make_cand(int c, int stav, const int* rm, int i, int t) {
    int h = c >> 2, k = c & 3;
    int r = rm[((i * Hn + h) * Kn + k) * TPn + t];
    return (stav ^ (1 << h)) ^ (r & ((1 << h) - 1));
}

__global__ __launch_bounds__(256, 6) void k_loss(const int* __restrict__ sta,
                                                 const int* __restrict__ rmask,
                                                 float* __restrict__ out) {
    int i = blockIdx.x, t = blockIdx.y;
    int tid = threadIdx.x;

    __shared__ uint2    s_pk[T2n];       // 4 KB
    __shared__ unsigned s_bm[2048];      // 8 KB presence bitmap over ap
    __shared__ int      s_bs[17];
    __shared__ float2   s_WN[16];

    int base = (i * TPn + t);
    if (tid < 17) s_bs[tid] = g_bs[base * 17 + tid];
    else if (tid >= 32 && tid < 48) s_WN[tid - 32] = g_WN[base * 16 + tid - 32];
    #pragma unroll
    for (int u = 0; u < 8; u++) s_bm[tid + 256 * u] = 0u;
    int cnt = __ldg(&g_bs[base * 17 + 16]);
    __syncthreads();

    const uint2* gp = g_pack + base * T2n;
    for (int idx = tid; idx < cnt; idx += 256) {
        uint2 e = gp[idx];
        s_pk[idx] = e;
        atomicOr(&s_bm[e.y >> 5], 1u << (e.y & 31));
    }
    __syncthreads();

    int c  = tid >> 2;                  // 0..63
    int q4 = tid & 3;
    int stav = sta[i * TPn + t];
    int cand = make_cand(c, stav, rmask, i, t);
    unsigned ac = (unsigned)(cand < 0 ? -cand : cand);
    int acH = (int)(ac >> 12);          // 0..16

    float S2 = 0.f, Sq = 0.f;

    // (a) bucket aggregates: 4 buckets per thread
    #pragma unroll
    for (int u = 0; u < 4; u++) {
        int b = q4 * 4 + u;
        if (b != acH) {
            int xh = acH ^ b;                               // 1..31
            int mb; asm("bfind.u32 %0, %1;" : "=r"(mb) : "r"(xh));
            float f = 8388611.0f - __int_as_float(mb | 0x4B000000);   // 3 - mb
            float2 wn = s_WN[b];
            S2 = fmaf(wn.x, f, S2);
            Sq = fmaf(wn.y, f * f, Sq);
        }
    }

    // (b) exact scan of matching bucket
    if (acH < 16) {
        int hi = s_bs[acH + 1];
        for (int k = s_bs[acH] + q4; k < hi; k += 4) {
            uint2 e = s_pk[k];
            unsigned v = (ac ^ e.y) + 1u;
            int qq; asm("bfind.u32 %0, %1;" : "=r"(qq) : "r"(v));
            float f = 8388623.0f - __int_as_float(qq | 0x4B000000);   // 15 - qq
            S2 = fmaf(__uint_as_float(e.x), f, S2);
            Sq = fmaf(f, f, Sq);
        }
    }

    // (c) ripple fixups: k = 13+q4; q4==0 also handles k=17
    #pragma unroll
    for (int pp = 0; pp < 2; pp++) {
        int kk = (pp == 0) ? (13 + q4) : 17;
        if (pp == 1 && q4 != 0) break;
        unsigned rv = ac ^ ((1u << kk) - 1u);
        if (rv <= 65535u) {
            if (s_bm[rv >> 5] & (1u << (rv & 31))) {
                int bb = (int)(rv >> 12);
                int lo = s_bs[bb], hi = s_bs[bb + 1];
                float dq = (float)(2 * kk - 31);
                for (int k = lo; k < hi; k++) {
                    uint2 e = s_pk[k];
                    if (e.y == rv) { S2 -= __uint_as_float(e.x); Sq += dq; }
                }
            }
        }
    }

    // quad reduce
    S2 += __shfl_down_sync(0xffffffffu, S2, 2, 4);
    S2 += __shfl_down_sync(0xffffffffu, S2, 1, 4);
    Sq += __shfl_down_sync(0xffffffffu, Sq, 2, 4);
    Sq += __shfl_down_sync(0xffffffffu, Sq, 1, 4);

    if (q4 == 0) {
        float SA = g_SA[base];
        float bse = SA + Sq * (1.0f / 16384.0f);
        float sc  = cand < 0 ? -1.0f : 1.0f;
        float tw  = 2.0f * sc * S2;
        float lp  = bse + tw;
        out[(i * Cn + c) * TPn + t] = lp;
        out[(i * Cn + 65 + c) * TPn + t] = (cand == 0) ? lp : (bse - tw);
    }
    if (tid == 0)
        out[(i * Cn + 64) * TPn + t] = g_L64[i];
}

// ---------------------------------------------------------------------------
extern "C" void kernel_launch(void* const* d_in, const int* in_sizes, int n_in,
                              void* d_out, int out_size) {
    const float*    emb1 = (const float*)d_in[0];
    const float*    emb2 = (const float*)d_in[1];
    const int*      sta  = (const int*)d_in[2];
    const int*      pos  = (const int*)d_in[3];
    const unsigned* mask = (const unsigned*)d_in[4];
    const int*      rm   = (const int*)d_in[5];
    float*          out  = (float*)d_out;

    k_val<<<dim3(8, 16), 512>>>(emb1, emb2);
    k_build<<<T1n, 512>>>(sta, pos, mask);
    k_loss<<<dim3(T1n, TPn), 256>>>(sta, rm, out);
}